// round 11
// baseline (speedup 1.0000x reference)
#include <cuda_runtime.h>
#include <math.h>

#define B_ 8
#define T_ 1024
#define D_ 512
#define H_ 8
#define BT_ (B_*T_)        /* 8192  */
#define BHT_ (B_*H_*T_)    /* 65536 */

// ---------------- scratch (static device arrays: sanctioned no-alloc workaround) ----
__device__ float g_Q128[(size_t)BHT_*128];
__device__ float g_K128[(size_t)BHT_*128];
__device__ float g_rq[BHT_];
__device__ float g_rk[BHT_];
__device__ float g_vm[(size_t)BHT_*64];
__device__ float g_vc[(size_t)BHT_*64];
__device__ float g_om[(size_t)BT_*D_];
__device__ float g_oc[(size_t)BT_*D_];

enum { M_PLAIN = 0, M_QKMEAN = 1, M_QKCOV = 2, M_V = 3 };

// ---------------------------------------------------------------------------
// SGEMM: Y[m,n] = sum_k X[m,k]*W[n,k] + bias[n].  M=8192,N=512,K=512.
// BM=BN=128, BK=16, 256 threads, 8x8 per thread (2x2 blocks of 4x4).
// ---------------------------------------------------------------------------
template <int MODE>
__global__ __launch_bounds__(256) void proj_gemm(
    const float* __restrict__ X, const float* __restrict__ W,
    const float* __restrict__ bias, float* __restrict__ out,
    float* __restrict__ rbuf)
{
    __shared__ __align__(16) float As[16][132];
    __shared__ __align__(16) float Bs[16][132];

    const int tid  = threadIdx.x;
    const int w    = tid >> 5, lane = tid & 31;
    const int wr   = w >> 1,  wc   = w & 1;
    const int lr   = lane >> 3, lc = lane & 7;
    const int r0   = wr * 32 + lr * 4;
    const int c0   = wc * 64 + lc * 4;

    const int m0 = blockIdx.x * 128, n0 = blockIdx.y * 128;

    const int sm_ = tid >> 2;
    const int sk_ = (tid & 3) * 4;

    const float* Xb = X + (size_t)m0 * 512;
    const float* Wb = W + (size_t)n0 * 512;

    float4 xa0 = *(const float4*)(Xb + (size_t)sm_ * 512 + sk_);
    float4 xa1 = *(const float4*)(Xb + (size_t)(sm_ + 64) * 512 + sk_);
    float4 wa0 = *(const float4*)(Wb + (size_t)sm_ * 512 + sk_);
    float4 wa1 = *(const float4*)(Wb + (size_t)(sm_ + 64) * 512 + sk_);

    float acc[8][8];
#pragma unroll
    for (int i = 0; i < 8; i++)
#pragma unroll
        for (int j = 0; j < 8; j++) acc[i][j] = 0.f;

    for (int k0 = 0; k0 < 512; k0 += 16) {
        As[sk_+0][sm_]    = xa0.x; As[sk_+1][sm_]    = xa0.y; As[sk_+2][sm_]    = xa0.z; As[sk_+3][sm_]    = xa0.w;
        As[sk_+0][sm_+64] = xa1.x; As[sk_+1][sm_+64] = xa1.y; As[sk_+2][sm_+64] = xa1.z; As[sk_+3][sm_+64] = xa1.w;
        Bs[sk_+0][sm_]    = wa0.x; Bs[sk_+1][sm_]    = wa0.y; Bs[sk_+2][sm_]    = wa0.z; Bs[sk_+3][sm_]    = wa0.w;
        Bs[sk_+0][sm_+64] = wa1.x; Bs[sk_+1][sm_+64] = wa1.y; Bs[sk_+2][sm_+64] = wa1.z; Bs[sk_+3][sm_+64] = wa1.w;
        __syncthreads();
        if (k0 + 16 < 512) {
            const int kn = k0 + 16;
            xa0 = *(const float4*)(Xb + (size_t)sm_ * 512 + kn + sk_);
            xa1 = *(const float4*)(Xb + (size_t)(sm_ + 64) * 512 + kn + sk_);
            wa0 = *(const float4*)(Wb + (size_t)sm_ * 512 + kn + sk_);
            wa1 = *(const float4*)(Wb + (size_t)(sm_ + 64) * 512 + kn + sk_);
        }
#pragma unroll
        for (int k = 0; k < 16; k++) {
            float4 a0 = *(const float4*)(&As[k][r0]);
            float4 a1 = *(const float4*)(&As[k][r0 + 16]);
            float4 b0 = *(const float4*)(&Bs[k][c0]);
            float4 b1 = *(const float4*)(&Bs[k][c0 + 32]);
            float av[8] = {a0.x,a0.y,a0.z,a0.w, a1.x,a1.y,a1.z,a1.w};
            float bv[8] = {b0.x,b0.y,b0.z,b0.w, b1.x,b1.y,b1.z,b1.w};
#pragma unroll
            for (int i = 0; i < 8; i++)
#pragma unroll
                for (int j = 0; j < 8; j++)
                    acc[i][j] = fmaf(av[i], bv[j], acc[i][j]);
        }
        __syncthreads();
    }

    float bsv[8];
#pragma unroll
    for (int j = 0; j < 8; j++)
        bsv[j] = bias[n0 + c0 + (j & 3) + (j >> 2) * 32];

    const int head = (n0 + c0) >> 6;
    const int cih  = c0 & 63;
    float part[8];
#pragma unroll
    for (int i = 0; i < 8; i++) part[i] = 0.f;

#pragma unroll
    for (int i = 0; i < 8; i++) {
        const int row = r0 + (i & 3) + (i >> 2) * 16;
        const int m = m0 + row;
        const int bb = m >> 10, tt = m & 1023;
        const int bhh = bb * 8 + head;
        float y[8];
#pragma unroll
        for (int j = 0; j < 8; j++) y[j] = acc[i][j] + bsv[j];

        if (MODE == M_PLAIN) {
            *(float4*)(out + (size_t)m * 512 + n0 + c0)      = make_float4(y[0],y[1],y[2],y[3]);
            *(float4*)(out + (size_t)m * 512 + n0 + c0 + 32) = make_float4(y[4],y[5],y[6],y[7]);
        } else if (MODE == M_V) {
            const size_t base = ((size_t)bhh * 1024 + tt) * 64;
            *(float4*)(out + base + cih)      = make_float4(y[0],y[1],y[2],y[3]);
            *(float4*)(out + base + cih + 32) = make_float4(y[4],y[5],y[6],y[7]);
        } else if (MODE == M_QKMEAN) {
            const size_t base = ((size_t)bhh * 1024 + tt) * 128;
            *(float4*)(out + base + cih)      = make_float4(y[0],y[1],y[2],y[3]);
            *(float4*)(out + base + cih + 32) = make_float4(y[4],y[5],y[6],y[7]);
#pragma unroll
            for (int j = 0; j < 8; j++) part[i] += y[j] * y[j];
        } else { // M_QKCOV
            const size_t base = ((size_t)bhh * 1024 + tt) * 128 + 64;
            float s[8];
#pragma unroll
            for (int j = 0; j < 8; j++) s[j] = sqrtf(fmaxf(y[j], 1e-24f));
            *(float4*)(out + base + cih)      = make_float4(s[0],s[1],s[2],s[3]);
            *(float4*)(out + base + cih + 32) = make_float4(s[4],s[5],s[6],s[7]);
#pragma unroll
            for (int j = 0; j < 8; j++) part[i] += y[j];
        }
    }

    if (MODE == M_QKMEAN || MODE == M_QKCOV) {
        float* red = &As[0][0];
#pragma unroll
        for (int i = 0; i < 8; i++) {
            const int row = r0 + (i & 3) + (i >> 2) * 16;
            red[row * 16 + wc * 8 + lc] = part[i];
        }
        __syncthreads();
        {
            const int row = tid & 127, half = tid >> 7;
            float ssum = 0.f;
#pragma unroll
            for (int x = 0; x < 8; x++) ssum += red[row * 16 + half * 8 + x];
            const int m = m0 + row;
            const int bb = m >> 10, tt = m & 1023;
            const int hh = (n0 >> 6) + half;
            const size_t idx = ((size_t)(bb * 8 + hh)) * 1024 + tt;
            if (MODE == M_QKMEAN) rbuf[idx] = ssum;
            else                  rbuf[idx] += ssum;
        }
    }
}

// ---------------------------------------------------------------------------
// Attention v2: block = (bh, 16 rows), 512 threads / 16 warps.
// Double-buffered 32x128 K / V tile staging; score rows in smem.
// P1: warp = 4 rows x 8 s.  P2-P4: warp-per-row.  P5: warp = 4 rows x 8 s
// with 4 dims/lane; 4-set partial reduce in smem.
// ---------------------------------------------------------------------------
__global__ __launch_bounds__(512) void attn_kernel(const float* __restrict__ gammas,
                                                   const int* __restrict__ zp_ptr)
{
    extern __shared__ __align__(16) float smem_[];
    float* sT[2] = { smem_, smem_ + 4224 };   // 2 x 32*132 tile buffers
    float* sQ    = smem_ + 8448;              // 16*132
    float* sRow  = smem_ + 10560;             // 16*1024 (later: partial scratch)
    float* sRq   = smem_ + 26944;             // 16
    float* sRk   = smem_ + 26960;             // 2 x 32
    float* sInv  = smem_ + 27024;             // 16

    const int bh    = blockIdx.x;
    const int b     = bh >> 3, h = bh & 7;
    const int w     = threadIdx.x >> 5, lane = threadIdx.x & 31;
    const int tbase = blockIdx.y * 16;
    const int ntiles = ((tbase + 15) >> 5) + 1;
    const int send   = ntiles * 32;

    // stage q rows (stride 132) + rq
    for (int v = threadIdx.x; v < 2048; v += 512)
        sQ[(v >> 7) * 132 + (v & 127)] =
            g_Q128[((size_t)bh * T_ + tbase + (v >> 7)) * 128 + (v & 127)];
    if (threadIdx.x < 16)
        sRq[threadIdx.x] = g_rq[(size_t)bh * T_ + tbase + threadIdx.x];

    const float* Kg = g_K128 + (size_t)bh * T_ * 128;

    // ---- P1: scores with double-buffered K staging ------------------------
    const int rloc = ((w & 3) << 2) | (lane >> 3);          // 0..15
    const int sloc = ((w >> 2) << 3) | (lane & 7);          // 0..31
    const float* qp = sQ + rloc * 132;

    // stage tile 0
    {
#pragma unroll
        for (int u = 0; u < 2; u++) {
            const int v = threadIdx.x + u * 512;
            const int sr = v >> 5, c4 = (v & 31) * 4;
            float4 kv = *(const float4*)(Kg + (size_t)sr * 128 + c4);
            float* d = sT[0] + sr * 132 + c4;
            d[0]=kv.x; d[1]=kv.y; d[2]=kv.z; d[3]=kv.w;
        }
        if (threadIdx.x < 32) sRk[threadIdx.x] = g_rk[(size_t)bh * T_ + threadIdx.x];
    }
    __syncthreads();

    for (int it = 0; it < ntiles; ++it) {
        const int buf = it & 1;
        if (it + 1 < ntiles) {
            const int s0n = (it + 1) * 32;
#pragma unroll
            for (int u = 0; u < 2; u++) {
                const int v = threadIdx.x + u * 512;
                const int sr = v >> 5, c4 = (v & 31) * 4;
                float4 kv = *(const float4*)(Kg + (size_t)(s0n + sr) * 128 + c4);
                float* d = sT[buf ^ 1] + sr * 132 + c4;
                d[0]=kv.x; d[1]=kv.y; d[2]=kv.z; d[3]=kv.w;
            }
            if (threadIdx.x < 32)
                sRk[(buf ^ 1) * 32 + threadIdx.x] = g_rk[(size_t)bh * T_ + s0n + threadIdx.x];
        }
        // compute current tile
        {
            const int s0 = it * 32;
            const float* kp = sT[buf] + sloc * 132;
            float a0=0.f, a1=0.f, a2=0.f, a3=0.f;
#pragma unroll
            for (int c = 0; c < 128; c += 16) {
                float4 qA = *(const float4*)(qp + c);      float4 kA = *(const float4*)(kp + c);
                float4 qB = *(const float4*)(qp + c + 4);  float4 kB = *(const float4*)(kp + c + 4);
                float4 qC = *(const float4*)(qp + c + 8);  float4 kC = *(const float4*)(kp + c + 8);
                float4 qD = *(const float4*)(qp + c + 12); float4 kD = *(const float4*)(kp + c + 12);
                a0 = fmaf(qA.x,kA.x,a0); a0 = fmaf(qA.y,kA.y,a0); a0 = fmaf(qA.z,kA.z,a0); a0 = fmaf(qA.w,kA.w,a0);
                a1 = fmaf(qB.x,kB.x,a1); a1 = fmaf(qB.y,kB.y,a1); a1 = fmaf(qB.z,kB.z,a1); a1 = fmaf(qB.w,kB.w,a1);
                a2 = fmaf(qC.x,kC.x,a2); a2 = fmaf(qC.y,kC.y,a2); a2 = fmaf(qC.z,kC.z,a2); a2 = fmaf(qC.w,kC.w,a2);
                a3 = fmaf(qD.x,kD.x,a3); a3 = fmaf(qD.y,kD.y,a3); a3 = fmaf(qD.z,kD.z,a3); a3 = fmaf(qD.w,kD.w,a3);
            }
            const float dot = (a0 + a1) + (a2 + a3);
            sRow[rloc * 1024 + s0 + sloc] =
                (2.f * dot - sRq[rloc] - sRk[buf * 32 + sloc]) * 0.125f;
        }
        __syncthreads();
    }

    // ---- P2-P4: warp-per-row ---------------------------------------------
    const int t = tbase + w;
    float* row = sRow + w * 1024;
    const float g  = gammas[h];
    const float sp = (g > 20.f) ? g : log1pf(__expf(g));
    const float gamma = -sp;

    float m1 = -3.4e38f;
    for (int s = lane; s <= t; s += 32) m1 = fmaxf(m1, row[s]);
#pragma unroll
    for (int o = 16; o; o >>= 1) m1 = fmaxf(m1, __shfl_xor_sync(0xffffffffu, m1, o));
    float den1 = 0.f;
    for (int s = lane; s <= t; s += 32) den1 += __expf(row[s] - m1);
#pragma unroll
    for (int o = 16; o; o >>= 1) den1 += __shfl_xor_sync(0xffffffffu, den1, o);
    const float inv1 = 1.f / den1;

    float carry = 0.f, m2 = -3.4e38f;
    for (int s0 = 0; s0 <= t; s0 += 32) {
        const int s = s0 + lane;
        const bool valid = (s <= t);
        const float sc = valid ? row[s] : 0.f;
        const float e  = valid ? __expf(sc - m1) : 0.f;
        float x = e;
#pragma unroll
        for (int d = 1; d < 32; d <<= 1) {
            float y = __shfl_up_sync(0xffffffffu, x, d);
            if (lane >= d) x += y;
        }
        const float tot = __shfl_sync(0xffffffffu, x, 31);
        const float cum = carry + x;
        carry += tot;
        if (valid) {
            const float tail = (den1 - cum) * inv1;
            const float pos  = (float)(t - s);
            const float dsc  = sqrtf(fmaxf(tail * pos, 0.f));
            float eff = __expf(gamma * dsc);
            eff = fminf(fmaxf(eff, 1e-5f), 1e5f);
            const float ns = sc * eff;
            row[s] = ns;
            m2 = fmaxf(m2, ns);
        }
    }
#pragma unroll
    for (int o = 16; o; o >>= 1) m2 = fmaxf(m2, __shfl_xor_sync(0xffffffffu, m2, o));

    float den2 = 0.f;
    for (int s0 = 0; s0 <= t; s0 += 32) {
        const int s = s0 + lane;
        const float e = (s <= t) ? __expf(row[s] - m2) : 0.f;
        row[s] = e;
        den2 += e;
    }
#pragma unroll
    for (int o = 16; o; o >>= 1) den2 += __shfl_xor_sync(0xffffffffu, den2, o);
    for (int s = t + 1 + lane; s < send; s += 32) row[s] = 0.f;   // P5 reads unguarded
    if (lane == 0) sInv[w] = 1.f / den2;
    __syncthreads();

    // ---- P5: P*V / P^2*Vc with double-buffered V staging ------------------
    const int rb  = (w & 3) * 4;       // row group (4 of 16)
    const int sq8 = (w >> 2) * 8;      // s offset inside tile
    const int d4  = lane * 4;          // concat dim: <64 mean, >=64 cov
    float pacc[4][4];
#pragma unroll
    for (int r = 0; r < 4; r++)
#pragma unroll
        for (int q = 0; q < 4; q++) pacc[r][q] = 0.f;

    const float* Vm = g_vm + (size_t)bh * T_ * 64;
    const float* Vc = g_vc + (size_t)bh * T_ * 64;

    // stage V tile 0
    {
#pragma unroll
        for (int u = 0; u < 2; u++) {
            const int v = threadIdx.x + u * 512;
            const int sr = v >> 5, c4 = (v & 31) * 4;
            float4 val = (c4 < 64)
                ? *(const float4*)(Vm + (size_t)sr * 64 + c4)
                : *(const float4*)(Vc + (size_t)sr * 64 + (c4 - 64));
            float* d = sT[0] + sr * 132 + c4;
            d[0]=val.x; d[1]=val.y; d[2]=val.z; d[3]=val.w;
        }
    }
    __syncthreads();

    for (int it = 0; it < ntiles; ++it) {
        const int buf = it & 1;
        if (it + 1 < ntiles) {
            const int s0n = (it + 1) * 32;
#pragma unroll
            for (int u = 0; u < 2; u++) {
                const int v = threadIdx.x + u * 512;
                const int sr = v >> 5, c4 = (v & 31) * 4;
                float4 val = (c4 < 64)
                    ? *(const float4*)(Vm + (size_t)(s0n + sr) * 64 + c4)
                    : *(const float4*)(Vc + (size_t)(s0n + sr) * 64 + (c4 - 64));
                float* d = sT[buf ^ 1] + sr * 132 + c4;
                d[0]=val.x; d[1]=val.y; d[2]=val.z; d[3]=val.w;
            }
        }
        {
            const int s0 = it * 32;
#pragma unroll
            for (int jj = 0; jj < 8; jj++) {
                const int j = sq8 + jj;
                const float4 v4 = *(const float4*)(sT[buf] + j * 132 + d4);
#pragma unroll
                for (int r = 0; r < 4; r++) {
                    const float e = sRow[(rb + r) * 1024 + s0 + j];
                    const float mlt = (d4 < 64) ? e : e * e;
                    pacc[r][0] = fmaf(mlt, v4.x, pacc[r][0]);
                    pacc[r][1] = fmaf(mlt, v4.y, pacc[r][1]);
                    pacc[r][2] = fmaf(mlt, v4.z, pacc[r][2]);
                    pacc[r][3] = fmaf(mlt, v4.w, pacc[r][3]);
                }
            }
        }
        __syncthreads();
    }

    // partial store (probs fully consumed; reuse sRow) + reduce
    const int pp = w >> 2;   // 0..3
#pragma unroll
    for (int r = 0; r < 4; r++)
        *(float4*)(sRow + pp * 2048 + (rb + r) * 128 + d4) =
            make_float4(pacc[r][0], pacc[r][1], pacc[r][2], pacc[r][3]);
    __syncthreads();

    {
        const int rr = threadIdx.x >> 5;          // 0..15
        const int dd = (threadIdx.x & 31) * 4;    // 0..124
        float4 p0 = *(const float4*)(sRow + 0 * 2048 + rr * 128 + dd);
        float4 p1 = *(const float4*)(sRow + 1 * 2048 + rr * 128 + dd);
        float4 p2 = *(const float4*)(sRow + 2 * 2048 + rr * 128 + dd);
        float4 p3 = *(const float4*)(sRow + 3 * 2048 + rr * 128 + dd);
        const int tt = tbase + rr;
        const float i2 = sInv[rr];
        float scale = (dd < 64) ? i2 : i2 * i2;
        if (tt == 0 && (*zp_ptr)) scale = 0.f;
        float4 res = make_float4((p0.x+p1.x+p2.x+p3.x) * scale,
                                 (p0.y+p1.y+p2.y+p3.y) * scale,
                                 (p0.z+p1.z+p2.z+p3.z) * scale,
                                 (p0.w+p1.w+p2.w+p3.w) * scale);
        const size_t ob = ((size_t)b * 1024 + tt) * 512 + h * 64;
        if (dd < 64) *(float4*)(g_om + ob + dd)      = res;
        else         *(float4*)(g_oc + ob + dd - 64) = res;
    }
}

// ---------------------------------------------------------------------------
extern "C" void kernel_launch(void* const* d_in, const int* in_sizes, int n_in,
                              void* d_out, int out_size)
{
    const float* q_mean  = (const float*)d_in[0];
    const float* q_cov   = (const float*)d_in[1];
    const float* k_mean  = (const float*)d_in[2];
    const float* k_cov   = (const float*)d_in[3];
    const float* v_mean  = (const float*)d_in[4];
    const float* v_cov   = (const float*)d_in[5];
    const float* Wk_mean = (const float*)d_in[6];
    const float* bk_mean = (const float*)d_in[7];
    const float* Wk_cov  = (const float*)d_in[8];
    const float* bk_cov  = (const float*)d_in[9];
    const float* Wv_mean = (const float*)d_in[10];
    const float* bv_mean = (const float*)d_in[11];
    const float* Wv_cov  = (const float*)d_in[12];
    const float* bv_cov  = (const float*)d_in[13];
    const float* Wo_mean = (const float*)d_in[14];
    const float* bo_mean = (const float*)d_in[15];
    const float* Wo_cov  = (const float*)d_in[16];
    const float* bo_cov  = (const float*)d_in[17];
    const float* gammas  = (const float*)d_in[18];
    const int*   zp      = (const int*)d_in[20];
    float* out = (float*)d_out;

    float *Q128, *K128, *rq, *rk, *vm, *vc, *om, *oc;
    cudaGetSymbolAddress((void**)&Q128, g_Q128);
    cudaGetSymbolAddress((void**)&K128, g_K128);
    cudaGetSymbolAddress((void**)&rq,   g_rq);
    cudaGetSymbolAddress((void**)&rk,   g_rk);
    cudaGetSymbolAddress((void**)&vm,   g_vm);
    cudaGetSymbolAddress((void**)&vc,   g_vc);
    cudaGetSymbolAddress((void**)&om,   g_om);
    cudaGetSymbolAddress((void**)&oc,   g_oc);

    dim3 gb(64, 4), tb(256);
    proj_gemm<M_QKMEAN><<<gb, tb>>>(q_mean, Wk_mean, bk_mean, Q128, rq);
    proj_gemm<M_QKCOV ><<<gb, tb>>>(q_cov,  Wk_cov,  bk_cov,  Q128, rq);
    proj_gemm<M_QKMEAN><<<gb, tb>>>(k_mean, Wk_mean, bk_mean, K128, rk);
    proj_gemm<M_QKCOV ><<<gb, tb>>>(k_cov,  Wk_cov,  bk_cov,  K128, rk);
    proj_gemm<M_V     ><<<gb, tb>>>(v_mean, Wv_mean, bv_mean, vm, nullptr);
    proj_gemm<M_V     ><<<gb, tb>>>(v_cov,  Wv_cov,  bv_cov,  vc, nullptr);

    const int smem = 27040 * 4;   // 108160 B -> 2 CTAs/SM
    cudaFuncSetAttribute(attn_kernel, cudaFuncAttributeMaxDynamicSharedMemorySize, smem);
    attn_kernel<<<dim3(64, 64), 512, smem>>>(gammas, zp);

    proj_gemm<M_PLAIN><<<gb, tb>>>(om, Wo_mean, bo_mean, out, nullptr);
    proj_gemm<M_PLAIN><<<gb, tb>>>(oc, Wo_cov,  bo_cov,  out + (size_t)BT_ * D_, nullptr);
}